// round 12
// baseline (speedup 1.0000x reference)
#include <cuda_runtime.h>
#include <math.h>

#define PS    16
#define HID   8
#define GRIDP 24
#define NPATCH 576      // 24*24
#define NB    2
#define HW    384
#define DIN   256
#define SCALE 0.35355339059327373f

#define TSTR  48        // tile row stride (floats)
#define MSTR  48        // moment row stride (u64): 8 slots x 6 u64
#define HMAX  8         // max halo (sigma cap 6 -> half <= 8)

typedef unsigned long long u64;

// ---------------- scratch (device globals; no allocation allowed) ----------
__device__ float g_q1[NB*NPATCH*HID];
__device__ float g_k1[NB*NPATCH*HID];
__device__ float g_v1[NB*NPATCH*HID];
__device__ float g_q2[NB*NPATCH*HID];    // pre-scaled by SCALE
__device__ float g_k2[NB*NPATCH*HID];
__device__ float g_v2[NB*NPATCH*HID];
__device__ float g_s [NB*NPATCH*3];
__device__ int   g_max;

// ---------------- packed f32x2 helpers (Blackwell) --------------------------
__device__ __forceinline__ u64 pk2(float lo, float hi){
    u64 r; asm("mov.b64 %0, {%1, %2};" : "=l"(r) : "f"(lo), "f"(hi)); return r;
}
__device__ __forceinline__ float2 upk2(u64 v){
    float2 f; asm("mov.b64 {%0, %1}, %2;" : "=f"(f.x), "=f"(f.y) : "l"(v)); return f;
}
__device__ __forceinline__ u64 fma2_(u64 a, u64 b, u64 c){
    u64 d; asm("fma.rn.f32x2 %0, %1, %2, %3;" : "=l"(d) : "l"(a), "l"(b), "l"(c)); return d;
}
__device__ __forceinline__ u64 mul2_(u64 a, u64 b){
    u64 d; asm("mul.rn.f32x2 %0, %1, %2;" : "=l"(d) : "l"(a), "l"(b)); return d;
}
__device__ __forceinline__ u64 add2_(u64 a, u64 b){
    u64 d; asm("add.rn.f32x2 %0, %1, %2;" : "=l"(d) : "l"(a), "l"(b)); return d;
}

// ---------------- qkv: 8 patches/block, smem-staged transposed W ------------
__global__ void qkv_kernel(const float* __restrict__ x,
                           const float* __restrict__ Wq, const float* __restrict__ bq,
                           const float* __restrict__ Wk, const float* __restrict__ bk,
                           const float* __restrict__ Wv, const float* __restrict__ bv) {
    __shared__ float sWq[DIN*9], sWk[DIN*9], sWv[DIN*9];   // [i*9 + col], pad 9
    __shared__ float sPat[8][DIN];
    const int n0 = blockIdx.x * 8, b = blockIdx.y;
    const int tid = threadIdx.x;
    if (blockIdx.x == 0 && b == 0 && tid == 0) g_max = 0;  // fold init

    #pragma unroll
    for (int e = tid; e < DIN*HID; e += 256) {
        int idx = (e >> 3)*9 + (e & 7);
        sWq[idx] = Wq[e]; sWk[idx] = Wk[e]; sWv[idx] = Wv[e];
    }
    const int r = tid >> 4, cc = tid & 15;
    #pragma unroll
    for (int p = 0; p < 8; p++) {
        int n = n0 + p;
        int hp = n / GRIDP, wn = n % GRIDP;
        sPat[p][tid] = x[(b*HW + hp*PS + r)*HW + wn*PS + cc];
    }
    __syncthreads();

    const int w = tid >> 5, lane = tid & 31;
    float aq[8], ak[8], av[8];
    #pragma unroll
    for (int p = 0; p < 8; p++) { aq[p] = 0.f; ak[p] = 0.f; av[p] = 0.f; }
    #pragma unroll
    for (int it = 0; it < DIN/32; ++it) {
        const int i = lane + 32*it;
        const float wq = sWq[i*9 + w], wk = sWk[i*9 + w], wv = sWv[i*9 + w];
        #pragma unroll
        for (int p = 0; p < 8; p++) {
            const float pv = sPat[p][i];
            aq[p] = fmaf(pv, wq, aq[p]);
            ak[p] = fmaf(pv, wk, ak[p]);
            av[p] = fmaf(pv, wv, av[p]);
        }
    }
    #pragma unroll
    for (int o = 16; o; o >>= 1) {
        #pragma unroll
        for (int p = 0; p < 8; p++) {
            aq[p] += __shfl_xor_sync(0xffffffffu, aq[p], o);
            ak[p] += __shfl_xor_sync(0xffffffffu, ak[p], o);
            av[p] += __shfl_xor_sync(0xffffffffu, av[p], o);
        }
    }
    if (lane < 8) {
        const int p = lane;
        const int base = (b*NPATCH + n0 + p)*HID + w;
        g_q1[base] = aq[p] + bq[w];
        g_k1[base] = ak[p] + bk[w];
        g_v1[base] = av[p] + bv[w];
    }
}

// ---------------- attention core: 1 query/warp, 32-wide key split ------------
__device__ __forceinline__ void attn_core32(const float* __restrict__ sK,
                                            const float* __restrict__ sV,
                                            const float4 qa, const float4 qb,
                                            int lane, float fo[HID]) {
    float sum = 0.f;
    float4 A = {0,0,0,0}, B = {0,0,0,0};
    #pragma unroll 6
    for (int i = 0; i < NPATCH/32; i++) {
        const int m = i*32 + lane;
        const float4* k4 = (const float4*)(sK + m*8);
        float4 ka = k4[0], kb = k4[1];
        float d = qa.x*ka.x;
        d = fmaf(qa.y, ka.y, d); d = fmaf(qa.z, ka.z, d); d = fmaf(qa.w, ka.w, d);
        d = fmaf(qb.x, kb.x, d); d = fmaf(qb.y, kb.y, d);
        d = fmaf(qb.z, kb.z, d); d = fmaf(qb.w, kb.w, d);
        const float e = __expf(d);
        sum += e;
        const float4* v4 = (const float4*)(sV + m*8);
        float4 va = v4[0], vb = v4[1];
        A.x = fmaf(e, va.x, A.x); A.y = fmaf(e, va.y, A.y);
        A.z = fmaf(e, va.z, A.z); A.w = fmaf(e, va.w, A.w);
        B.x = fmaf(e, vb.x, B.x); B.y = fmaf(e, vb.y, B.y);
        B.z = fmaf(e, vb.z, B.z); B.w = fmaf(e, vb.w, B.w);
    }
    #pragma unroll
    for (int o = 16; o >= 1; o >>= 1) {
        sum += __shfl_xor_sync(0xffffffffu, sum, o);
        A.x += __shfl_xor_sync(0xffffffffu, A.x, o);
        A.y += __shfl_xor_sync(0xffffffffu, A.y, o);
        A.z += __shfl_xor_sync(0xffffffffu, A.z, o);
        A.w += __shfl_xor_sync(0xffffffffu, A.w, o);
        B.x += __shfl_xor_sync(0xffffffffu, B.x, o);
        B.y += __shfl_xor_sync(0xffffffffu, B.y, o);
        B.z += __shfl_xor_sync(0xffffffffu, B.z, o);
        B.w += __shfl_xor_sync(0xffffffffu, B.w, o);
    }
    const float inv = 1.f / sum;
    fo[0]=A.x*inv; fo[1]=A.y*inv; fo[2]=A.z*inv; fo[3]=A.w*inv;
    fo[4]=B.x*inv; fo[5]=B.y*inv; fo[6]=B.z*inv; fo[7]=B.w*inv;
}

// ---------------- attention stage 0 + projection epilogue --------------------
__global__ void attn0_kernel(const float* __restrict__ Wsq, const float* __restrict__ bsq,
                             const float* __restrict__ Wsk, const float* __restrict__ bsk,
                             const float* __restrict__ Wsv, const float* __restrict__ bsv) {
    __shared__ float sW[3][72];                 // 64 weights + 8 bias each
    __shared__ __align__(16) float sK[NPATCH*8];
    __shared__ __align__(16) float sV[NPATCH*8];
    const int b = blockIdx.y;
    const int tid = threadIdx.x;

    // PDL preamble: weight tables depend only on kernel args
    if (tid < 64) {
        sW[0][tid] = Wsq[tid]; sW[1][tid] = Wsk[tid]; sW[2][tid] = Wsv[tid];
    } else if (tid < 72) {
        int j = tid - 64;
        sW[0][64+j] = bsq[j]; sW[1][64+j] = bsk[j]; sW[2][64+j] = bsv[j];
    }
    cudaGridDependencySynchronize();            // wait for qkv's g_q1/k1/v1

    const float4* k4g = (const float4*)(g_k1 + b*NPATCH*HID);
    const float4* v4g = (const float4*)(g_v1 + b*NPATCH*HID);
    #pragma unroll
    for (int t = tid; t < NPATCH*2; t += 256) {
        ((float4*)sK)[t] = k4g[t];
        ((float4*)sV)[t] = v4g[t];
    }
    __syncthreads();

    const int w = tid >> 5, lane = tid & 31;
    const int qi = blockIdx.x*8 + w;

    const float4* q4 = (const float4*)(g_q1 + (b*NPATCH + qi)*HID);
    float4 qa = q4[0], qb = q4[1];
    qa.x *= SCALE; qa.y *= SCALE; qa.z *= SCALE; qa.w *= SCALE;
    qb.x *= SCALE; qb.y *= SCALE; qb.z *= SCALE; qb.w *= SCALE;

    float fo[HID];
    attn_core32(sK, sV, qa, qb, lane, fo);

    if (lane < 24) {
        const int mode = lane >> 3, col = lane & 7;
        const float* W = sW[mode];
        float o = W[64 + col];
        #pragma unroll
        for (int i = 0; i < HID; i++) o = fmaf(fo[i], W[i*HID + col], o);
        const int base = (b*NPATCH + qi)*HID + col;
        if (mode == 0)      g_q2[base] = o * SCALE;
        else if (mode == 1) g_k2[base] = o;
        else                g_v2[base] = o;
    }
}

// ---------------- attention stage 1 + LN + sigma head ------------------------
__global__ void attn1_kernel(const float* __restrict__ ln_g, const float* __restrict__ ln_b,
                             const float* __restrict__ Wp,   const float* __restrict__ bp) {
    __shared__ __align__(16) float sK[NPATCH*8];
    __shared__ __align__(16) float sV[NPATCH*8];
    const int b = blockIdx.y;
    const int tid = threadIdx.x;

    cudaGridDependencySynchronize();            // wait for attn0's g_q2/k2/v2

    const float4* k4g = (const float4*)(g_k2 + b*NPATCH*HID);
    const float4* v4g = (const float4*)(g_v2 + b*NPATCH*HID);
    #pragma unroll
    for (int t = tid; t < NPATCH*2; t += 256) {
        ((float4*)sK)[t] = k4g[t];
        ((float4*)sV)[t] = v4g[t];
    }
    __syncthreads();

    const int w = tid >> 5, lane = tid & 31;
    const int qi = blockIdx.x*8 + w;

    const float4* q4 = (const float4*)(g_q2 + (b*NPATCH + qi)*HID);
    const float4 qa = q4[0], qb = q4[1];     // pre-scaled in attn0

    float fo[HID];
    attn_core32(sK, sV, qa, qb, lane, fo);

    float mu = 0.f;
    #pragma unroll
    for (int j = 0; j < HID; j++) mu += fo[j];
    mu *= 0.125f;
    float var = 0.f;
    #pragma unroll
    for (int j = 0; j < HID; j++) { float d = fo[j]-mu; var = fmaf(d,d,var); }
    var *= 0.125f;
    const float rstd = rsqrtf(var + 1e-5f);

    float sig = 0.f;
    if (lane < 3) {
        float sv = bp[lane];
        #pragma unroll
        for (int i = 0; i < HID; i++) {
            const float oin = (fo[i]-mu)*rstd*ln_g[i] + ln_b[i];
            sv = fmaf(oin, Wp[i*3 + lane], sv);
        }
        float spv = (sv > 20.f) ? sv : log1pf(expf(sv));
        sig = fminf(spv, 6.0f) + 1e-6f;
        g_s[(b*NPATCH + qi)*3 + lane] = sig;
    }
    const float other = __shfl_xor_sync(0xffffffffu, sig, 1);
    if (lane == 0)
        atomicMax(&g_max, __float_as_int(fmaxf(sig, other)));  // positive floats: int order ok
}

// ---------------- bilateral: separable moment method, fixed-window staging ---
// Tile staged as fixed 32x32 (half=HMAX) BEFORE the PDL sync; the core uses a
// COMPILE-TIME offset OFF = HMAX - HALF (all indexing/parity static again).
template<int K>
__device__ __forceinline__ void bilat_core2(
    const float* __restrict__ tE, const float* __restrict__ tO,
    u64* __restrict__ sM2,
    const u64* __restrict__ sex2, const u64* __restrict__ sey2,
    const float* __restrict__ sS0,
    int tid, float c1c, float c2c, float* __restrict__ outrow)
{
    constexpr int HALF = (K-1)/2;
    constexpr int T = PS + 2*HALF;     // <= 32
    constexpr int OFF = HMAX - HALF;   // compile-time window offset
    constexpr bool ODD = (OFF & 1);

    // ---- horizontal: moments m1..m5 per (row, column-pair); one point/thread
    if (tid < 8*T) {
        const int row = tid >> 3, pr = tid & 7;
        const int base = (row + OFF)*TSTR + pr*2 + OFF;
        const float* eB = ODD ? (tO + base - 1) : (tE + base);
        const float* oB = ODD ? (tE + base + 1) : (tO + base);
        u64 m1=0ull, m2=0ull, m3=0ull, m4=0ull, m5=0ull;
        #pragma unroll
        for (int dx = 0; dx < K; dx++) {
            const u64 p2 = (dx & 1) ? *(const u64*)(oB + dx - 1)
                                    : *(const u64*)(eB + dx);
            const u64 e2 = sex2[dx];
            u64 t = mul2_(e2, p2);
            m1 = add2_(m1, t);
            t = mul2_(t, p2); m2 = add2_(m2, t);
            t = mul2_(t, p2); m3 = add2_(m3, t);
            t = mul2_(t, p2); m4 = add2_(m4, t);
            t = mul2_(t, p2); m5 = add2_(m5, t);
        }
        u64* d = sM2 + row*MSTR + pr*6;
        ((ulonglong2*)d)[0] = make_ulonglong2(m1, m2);
        ((ulonglong2*)d)[1] = make_ulonglong2(m3, m4);
        ((ulonglong2*)d)[2] = make_ulonglong2(m5, m5);
    }
    __syncthreads();
    if (tid >= 128) return;

    // ---- vertical: S1..S5 per pixel pair (conflict-free LDS.128) ----
    const int r = tid >> 3, pr = tid & 7;
    u64 S1=0ull, S2=0ull, S3=0ull, S4=0ull, S5=0ull;
    #pragma unroll
    for (int dy = 0; dy < K; dy++) {
        const u64 ey2 = sey2[dy];
        const u64* mr = sM2 + (r + dy)*MSTR + pr*6;
        const ulonglong2 L0 = ((const ulonglong2*)mr)[0];
        const ulonglong2 L1 = ((const ulonglong2*)mr)[1];
        const u64 m5 = mr[4];
        S1 = fma2_(ey2, L0.x, S1);
        S2 = fma2_(ey2, L0.y, S2);
        S3 = fma2_(ey2, L1.x, S3);
        S4 = fma2_(ey2, L1.y, S4);
        S5 = fma2_(ey2, m5,   S5);
    }

    // ---- combine: center index (r+HMAX)*TSTR + pr*2 + HMAX (even -> tE) ----
    const u64 c2v = *(const u64*)(tE + (r + HMAX)*TSTR + pr*2 + HMAX);
    const u64 C1v  = pk2(c1c, c1c);
    const u64 C2v  = pk2(c2c, c2c);
    const u64 ONE2 = pk2(1.f, 1.f);
    const u64 cc2 = mul2_(c2v, c2v);
    const u64 cc4 = mul2_(cc2, cc2);
    const u64 a0 = fma2_(C2v, cc4, fma2_(C1v, cc2, ONE2));
    const u64 t1 = fma2_(pk2(2.f*c2c, 2.f*c2c), cc2, C1v);
    const u64 a1 = mul2_(mul2_(pk2(-2.f,-2.f), c2v), t1);
    const u64 a2 = fma2_(pk2(6.f*c2c, 6.f*c2c), cc2, C1v);
    const u64 a3 = mul2_(pk2(-4.f*c2c, -4.f*c2c), c2v);
    const float s0 = *sS0;
    const u64 S0v = pk2(s0, s0);
    u64 ws = mul2_(a0, S0v);
    ws = fma2_(a1, S1, ws);
    ws = fma2_(a2, S2, ws);
    ws = fma2_(a3, S3, ws);
    ws = fma2_(C2v, S4, ws);
    u64 ac = mul2_(a0, S1);
    ac = fma2_(a1, S2, ac);
    ac = fma2_(a2, S3, ac);
    ac = fma2_(a3, S4, ac);
    ac = fma2_(C2v, S5, ac);
    const float2 wv = upk2(ws), av = upk2(ac);
    float2 res;
    res.x = av.x / (wv.x + 1e-8f);
    res.y = av.y / (wv.y + 1e-8f);
    *(float2*)(outrow + r*HW + pr*2) = res;
}

__global__ void bilateral_kernel(const float* __restrict__ x, float* __restrict__ out) {
    __shared__ __align__(16) float tE[32*TSTR];
    __shared__ __align__(16) float tO[32*TSTR];
    __shared__ __align__(16) u64 sM2[32*MSTR];
    __shared__ u64 sex2[20], sey2[20];
    __shared__ float sS0;
    const int n = blockIdx.x, b = blockIdx.y;
    const int hp = n / GRIDP, wn = n % GRIDP;
    const int tid = threadIdx.x;

    // PDL preamble: stage fixed 32x32 window (depends only on x)
    const int y0m = hp*PS - HMAX, x0m = wn*PS - HMAX;
    const float* xb = x + b*HW*HW;
    #pragma unroll
    for (int i = tid; i < 1024; i += 256) {
        const int ty = i >> 5, tx = i & 31;
        const int gy = y0m + ty, gx = x0m + tx;
        float v = 0.f;
        if ((unsigned)gy < HW && (unsigned)gx < HW) v = xb[gy*HW + gx];
        tE[ty*TSTR + tx] = v;
        if (tx > 0) tO[ty*TSTR + tx - 1] = v;
    }
    cudaGridDependencySynchronize();            // wait for attn1's g_s/g_max

    const float m = __int_as_float(g_max);
    const int half = (int)ceilf(m + 1.0f);
    const int k = 2*half + 1;

    const float* sv = g_s + (b*NPATCH + n)*3;
    const float sx = sv[0], sy = sv[1], sr = sv[2];
    const float ix = -0.5f/(sx*sx), iy = -0.5f/(sy*sy), ir = -0.5f/(sr*sr);
    const float c1c = ir, c2c = 0.5f*ir*ir;

    if (tid < k) {
        const float f = (float)(tid - half);
        const float ex = __expf(f*f*ix);
        const float ey = __expf(f*f*iy);
        sex2[tid] = pk2(ex, ex);
        sey2[tid] = pk2(ey, ey);
    }
    __syncthreads();
    if (tid == 0) {
        float se = 0.f, sy2 = 0.f;
        for (int i = 0; i < k; i++) {
            se  += upk2(sex2[i]).x;
            sy2 += upk2(sey2[i]).x;
        }
        sS0 = se * sy2;
    }

    float* outrow = out + (b*HW + hp*PS)*HW + wn*PS;
    switch (k) {
        case 3:  bilat_core2<3 >(tE, tO, sM2, sex2, sey2, &sS0, tid, c1c, c2c, outrow); break;
        case 5:  bilat_core2<5 >(tE, tO, sM2, sex2, sey2, &sS0, tid, c1c, c2c, outrow); break;
        case 7:  bilat_core2<7 >(tE, tO, sM2, sex2, sey2, &sS0, tid, c1c, c2c, outrow); break;
        case 9:  bilat_core2<9 >(tE, tO, sM2, sex2, sey2, &sS0, tid, c1c, c2c, outrow); break;
        case 11: bilat_core2<11>(tE, tO, sM2, sex2, sey2, &sS0, tid, c1c, c2c, outrow); break;
        case 13: bilat_core2<13>(tE, tO, sM2, sex2, sey2, &sS0, tid, c1c, c2c, outrow); break;
        case 15: bilat_core2<15>(tE, tO, sM2, sex2, sey2, &sS0, tid, c1c, c2c, outrow); break;
        case 17: bilat_core2<17>(tE, tO, sM2, sex2, sey2, &sS0, tid, c1c, c2c, outrow); break;
        default: {   // generic fallback (unreachable: sigma cap bounds k <= 17)
            const int off = HMAX - half;
            const int r = tid >> 4, cc = tid & 15;
            const float c = tE[(r + half + off)*TSTR + cc + half + off];
            float acc = 0.f, wsum = 0.f;
            for (int dy = 0; dy < k; dy++) {
                const float fy = (float)(dy - half);
                const float ey = __expf(fy*fy*iy);
                const float* trow = tE + (r + dy + off)*TSTR + cc + off;
                for (int dx = 0; dx < k; dx++) {
                    const float fx = (float)(dx - half);
                    const float p = trow[dx];
                    const float d = c - p;
                    const float w = ey * __expf(fx*fx*ix) * __expf(d*d*ir);
                    wsum += w;
                    acc = fmaf(w, p, acc);
                }
            }
            outrow[r*HW + cc] = acc / (wsum + 1e-8f);
        }
    }
}

// ---------------- PDL launch helper ------------------------------------------
static void launch_pdl(const void* func, dim3 grid, dim3 block, void** args) {
    cudaLaunchConfig_t cfg = {};
    cfg.gridDim = grid;
    cfg.blockDim = block;
    cudaLaunchAttribute attr[1];
    attr[0].id = cudaLaunchAttributeProgrammaticStreamSerialization;
    attr[0].val.programmaticStreamSerializationAllowed = 1;
    cfg.attrs = attr;
    cfg.numAttrs = 1;
    if (cudaLaunchKernelExC(&cfg, func, args) != cudaSuccess) {
        cudaGetLastError();                      // clear; fall back to plain launch
        cudaLaunchKernel(func, grid, block, args, 0, 0);
    }
}

// ---------------- launcher ---------------------------------------------------
extern "C" void kernel_launch(void* const* d_in, const int* in_sizes, int n_in,
                              void* d_out, int out_size) {
    const float* x    = (const float*)d_in[0];
    const float* Wq   = (const float*)d_in[1];
    const float* bq   = (const float*)d_in[2];
    const float* Wk   = (const float*)d_in[3];
    const float* bk   = (const float*)d_in[4];
    const float* Wv   = (const float*)d_in[5];
    const float* bv   = (const float*)d_in[6];
    const float* Wsq  = (const float*)d_in[7];
    const float* bsq  = (const float*)d_in[8];
    const float* Wsk  = (const float*)d_in[9];
    const float* bsk  = (const float*)d_in[10];
    const float* Wsv  = (const float*)d_in[11];
    const float* bsv  = (const float*)d_in[12];
    const float* ln_g = (const float*)d_in[13];
    const float* ln_b = (const float*)d_in[14];
    const float* Wp   = (const float*)d_in[15];
    const float* bp   = (const float*)d_in[16];
    float* out = (float*)d_out;

    // qkv: plain launch (PDL here would race the previous replay's bilateral)
    qkv_kernel<<<dim3(NPATCH/8, NB), 256>>>(x, Wq, bq, Wk, bk, Wv, bv);

    {   // attn0 with PDL over qkv
        void* args[] = {(void*)&Wsq, (void*)&bsq, (void*)&Wsk, (void*)&bsk,
                        (void*)&Wsv, (void*)&bsv};
        launch_pdl((const void*)attn0_kernel, dim3(NPATCH/8, NB), dim3(256), args);
    }
    {   // attn1 with PDL over attn0
        void* args[] = {(void*)&ln_g, (void*)&ln_b, (void*)&Wp, (void*)&bp};
        launch_pdl((const void*)attn1_kernel, dim3(NPATCH/8, NB), dim3(256), args);
    }
    {   // bilateral with PDL over attn1 (tile staging overlaps attn1)
        void* args[] = {(void*)&x, (void*)&out};
        launch_pdl((const void*)bilateral_kernel, dim3(NPATCH, NB), dim3(256), args);
    }
}

// round 14
// speedup vs baseline: 1.0013x; 1.0013x over previous
#include <cuda_runtime.h>
#include <math.h>

#define PS    16
#define HID   8
#define GRIDP 24
#define NPATCH 576      // 24*24
#define NB    2
#define HW    384
#define DIN   256
#define SCALE 0.35355339059327373f

#define TSTR  48        // tile row stride (floats)
#define MSTR  48        // moment row stride (u64): 8 slots x 6 u64

typedef unsigned long long u64;

// ---------------- scratch (device globals; no allocation allowed) ----------
__device__ float g_q1[NB*NPATCH*HID];
__device__ float g_k1[NB*NPATCH*HID];
__device__ float g_v1[NB*NPATCH*HID];
__device__ float g_q2[NB*NPATCH*HID];    // pre-scaled by SCALE
__device__ float g_k2[NB*NPATCH*HID];
__device__ float g_v2[NB*NPATCH*HID];
__device__ float g_s [NB*NPATCH*3];
__device__ int   g_max;

// ---------------- packed f32x2 helpers (Blackwell) --------------------------
__device__ __forceinline__ u64 pk2(float lo, float hi){
    u64 r; asm("mov.b64 %0, {%1, %2};" : "=l"(r) : "f"(lo), "f"(hi)); return r;
}
__device__ __forceinline__ float2 upk2(u64 v){
    float2 f; asm("mov.b64 {%0, %1}, %2;" : "=f"(f.x), "=f"(f.y) : "l"(v)); return f;
}
__device__ __forceinline__ u64 fma2_(u64 a, u64 b, u64 c){
    u64 d; asm("fma.rn.f32x2 %0, %1, %2, %3;" : "=l"(d) : "l"(a), "l"(b), "l"(c)); return d;
}
__device__ __forceinline__ u64 mul2_(u64 a, u64 b){
    u64 d; asm("mul.rn.f32x2 %0, %1, %2;" : "=l"(d) : "l"(a), "l"(b)); return d;
}
__device__ __forceinline__ u64 add2_(u64 a, u64 b){
    u64 d; asm("add.rn.f32x2 %0, %1, %2;" : "=l"(d) : "l"(a), "l"(b)); return d;
}

// ---------------- qkv: 8 patches/block, smem-staged transposed W ------------
__global__ void qkv_kernel(const float* __restrict__ x,
                           const float* __restrict__ Wq, const float* __restrict__ bq,
                           const float* __restrict__ Wk, const float* __restrict__ bk,
                           const float* __restrict__ Wv, const float* __restrict__ bv) {
    __shared__ float sWq[DIN*9], sWk[DIN*9], sWv[DIN*9];   // [i*9 + col], pad 9
    __shared__ float sPat[8][DIN];
    const int n0 = blockIdx.x * 8, b = blockIdx.y;
    const int tid = threadIdx.x;
    if (blockIdx.x == 0 && b == 0 && tid == 0) g_max = 0;  // fold init

    #pragma unroll
    for (int e = tid; e < DIN*HID; e += 256) {
        int idx = (e >> 3)*9 + (e & 7);
        sWq[idx] = Wq[e]; sWk[idx] = Wk[e]; sWv[idx] = Wv[e];
    }
    const int r = tid >> 4, cc = tid & 15;
    #pragma unroll
    for (int p = 0; p < 8; p++) {
        int n = n0 + p;
        int hp = n / GRIDP, wn = n % GRIDP;
        sPat[p][tid] = x[(b*HW + hp*PS + r)*HW + wn*PS + cc];
    }
    __syncthreads();

    const int w = tid >> 5, lane = tid & 31;
    float aq[8], ak[8], av[8];
    #pragma unroll
    for (int p = 0; p < 8; p++) { aq[p] = 0.f; ak[p] = 0.f; av[p] = 0.f; }
    #pragma unroll
    for (int it = 0; it < DIN/32; ++it) {
        const int i = lane + 32*it;
        const float wq = sWq[i*9 + w], wk = sWk[i*9 + w], wv = sWv[i*9 + w];
        #pragma unroll
        for (int p = 0; p < 8; p++) {
            const float pv = sPat[p][i];
            aq[p] = fmaf(pv, wq, aq[p]);
            ak[p] = fmaf(pv, wk, ak[p]);
            av[p] = fmaf(pv, wv, av[p]);
        }
    }
    #pragma unroll
    for (int o = 16; o; o >>= 1) {
        #pragma unroll
        for (int p = 0; p < 8; p++) {
            aq[p] += __shfl_xor_sync(0xffffffffu, aq[p], o);
            ak[p] += __shfl_xor_sync(0xffffffffu, ak[p], o);
            av[p] += __shfl_xor_sync(0xffffffffu, av[p], o);
        }
    }
    if (lane < 8) {
        const int p = lane;
        const int base = (b*NPATCH + n0 + p)*HID + w;
        g_q1[base] = aq[p] + bq[w];
        g_k1[base] = ak[p] + bk[w];
        g_v1[base] = av[p] + bv[w];
    }
}

// ---------------- attention core: 1 query/warp, 32-wide key split ------------
__device__ __forceinline__ void attn_core32(const float* __restrict__ sK,
                                            const float* __restrict__ sV,
                                            const float4 qa, const float4 qb,
                                            int lane, float fo[HID]) {
    float sum = 0.f;
    float4 A = {0,0,0,0}, B = {0,0,0,0};
    #pragma unroll 6
    for (int i = 0; i < NPATCH/32; i++) {
        const int m = i*32 + lane;
        const float4* k4 = (const float4*)(sK + m*8);
        float4 ka = k4[0], kb = k4[1];
        float d = qa.x*ka.x;
        d = fmaf(qa.y, ka.y, d); d = fmaf(qa.z, ka.z, d); d = fmaf(qa.w, ka.w, d);
        d = fmaf(qb.x, kb.x, d); d = fmaf(qb.y, kb.y, d);
        d = fmaf(qb.z, kb.z, d); d = fmaf(qb.w, kb.w, d);
        const float e = __expf(d);
        sum += e;
        const float4* v4 = (const float4*)(sV + m*8);
        float4 va = v4[0], vb = v4[1];
        A.x = fmaf(e, va.x, A.x); A.y = fmaf(e, va.y, A.y);
        A.z = fmaf(e, va.z, A.z); A.w = fmaf(e, va.w, A.w);
        B.x = fmaf(e, vb.x, B.x); B.y = fmaf(e, vb.y, B.y);
        B.z = fmaf(e, vb.z, B.z); B.w = fmaf(e, vb.w, B.w);
    }
    #pragma unroll
    for (int o = 16; o >= 1; o >>= 1) {
        sum += __shfl_xor_sync(0xffffffffu, sum, o);
        A.x += __shfl_xor_sync(0xffffffffu, A.x, o);
        A.y += __shfl_xor_sync(0xffffffffu, A.y, o);
        A.z += __shfl_xor_sync(0xffffffffu, A.z, o);
        A.w += __shfl_xor_sync(0xffffffffu, A.w, o);
        B.x += __shfl_xor_sync(0xffffffffu, B.x, o);
        B.y += __shfl_xor_sync(0xffffffffu, B.y, o);
        B.z += __shfl_xor_sync(0xffffffffu, B.z, o);
        B.w += __shfl_xor_sync(0xffffffffu, B.w, o);
    }
    const float inv = 1.f / sum;
    fo[0]=A.x*inv; fo[1]=A.y*inv; fo[2]=A.z*inv; fo[3]=A.w*inv;
    fo[4]=B.x*inv; fo[5]=B.y*inv; fo[6]=B.z*inv; fo[7]=B.w*inv;
}

// ---------------- attention stage 0 + projection epilogue --------------------
__global__ void attn0_kernel(const float* __restrict__ Wsq, const float* __restrict__ bsq,
                             const float* __restrict__ Wsk, const float* __restrict__ bsk,
                             const float* __restrict__ Wsv, const float* __restrict__ bsv) {
    __shared__ float sW[3][72];                 // 64 weights + 8 bias each
    __shared__ __align__(16) float sK[NPATCH*8];
    __shared__ __align__(16) float sV[NPATCH*8];
    const int b = blockIdx.y;
    const int tid = threadIdx.x;

    // PDL preamble: weight tables depend only on kernel args
    if (tid < 64) {
        sW[0][tid] = Wsq[tid]; sW[1][tid] = Wsk[tid]; sW[2][tid] = Wsv[tid];
    } else if (tid < 72) {
        int j = tid - 64;
        sW[0][64+j] = bsq[j]; sW[1][64+j] = bsk[j]; sW[2][64+j] = bsv[j];
    }
    cudaGridDependencySynchronize();            // wait for qkv's g_q1/k1/v1

    const float4* k4g = (const float4*)(g_k1 + b*NPATCH*HID);
    const float4* v4g = (const float4*)(g_v1 + b*NPATCH*HID);
    #pragma unroll
    for (int t = tid; t < NPATCH*2; t += 256) {
        ((float4*)sK)[t] = k4g[t];
        ((float4*)sV)[t] = v4g[t];
    }
    __syncthreads();

    const int w = tid >> 5, lane = tid & 31;
    const int qi = blockIdx.x*8 + w;

    const float4* q4 = (const float4*)(g_q1 + (b*NPATCH + qi)*HID);
    float4 qa = q4[0], qb = q4[1];
    qa.x *= SCALE; qa.y *= SCALE; qa.z *= SCALE; qa.w *= SCALE;
    qb.x *= SCALE; qb.y *= SCALE; qb.z *= SCALE; qb.w *= SCALE;

    float fo[HID];
    attn_core32(sK, sV, qa, qb, lane, fo);

    if (lane < 24) {
        const int mode = lane >> 3, col = lane & 7;
        const float* W = sW[mode];
        float o = W[64 + col];
        #pragma unroll
        for (int i = 0; i < HID; i++) o = fmaf(fo[i], W[i*HID + col], o);
        const int base = (b*NPATCH + qi)*HID + col;
        if (mode == 0)      g_q2[base] = o * SCALE;
        else if (mode == 1) g_k2[base] = o;
        else                g_v2[base] = o;
    }
}

// ---------------- attention stage 1 + LN + sigma head ------------------------
__global__ void attn1_kernel(const float* __restrict__ ln_g, const float* __restrict__ ln_b,
                             const float* __restrict__ Wp,   const float* __restrict__ bp) {
    __shared__ __align__(16) float sK[NPATCH*8];
    __shared__ __align__(16) float sV[NPATCH*8];
    const int b = blockIdx.y;
    const int tid = threadIdx.x;

    cudaGridDependencySynchronize();            // wait for attn0's g_q2/k2/v2

    const float4* k4g = (const float4*)(g_k2 + b*NPATCH*HID);
    const float4* v4g = (const float4*)(g_v2 + b*NPATCH*HID);
    #pragma unroll
    for (int t = tid; t < NPATCH*2; t += 256) {
        ((float4*)sK)[t] = k4g[t];
        ((float4*)sV)[t] = v4g[t];
    }
    __syncthreads();

    const int w = tid >> 5, lane = tid & 31;
    const int qi = blockIdx.x*8 + w;

    const float4* q4 = (const float4*)(g_q2 + (b*NPATCH + qi)*HID);
    const float4 qa = q4[0], qb = q4[1];     // pre-scaled in attn0

    float fo[HID];
    attn_core32(sK, sV, qa, qb, lane, fo);

    float mu = 0.f;
    #pragma unroll
    for (int j = 0; j < HID; j++) mu += fo[j];
    mu *= 0.125f;
    float var = 0.f;
    #pragma unroll
    for (int j = 0; j < HID; j++) { float d = fo[j]-mu; var = fmaf(d,d,var); }
    var *= 0.125f;
    const float rstd = rsqrtf(var + 1e-5f);

    float sig = 0.f;
    if (lane < 3) {
        float sv = bp[lane];
        #pragma unroll
        for (int i = 0; i < HID; i++) {
            const float oin = (fo[i]-mu)*rstd*ln_g[i] + ln_b[i];
            sv = fmaf(oin, Wp[i*3 + lane], sv);
        }
        float spv = (sv > 20.f) ? sv : log1pf(expf(sv));
        sig = fminf(spv, 6.0f) + 1e-6f;
        g_s[(b*NPATCH + qi)*3 + lane] = sig;
    }
    const float other = __shfl_xor_sync(0xffffffffu, sig, 1);
    if (lane == 0)
        atomicMax(&g_max, __float_as_int(fmaxf(sig, other)));  // positive floats: int order ok
}

// ---------------- bilateral: separable moment method (R8 structure) ----------
// Moment slots: 6 u64 (48B, 16B-aligned) -> conflict-free LDS.128 vertical.
template<int K>
__device__ __forceinline__ void bilat_core2(
    const float* __restrict__ tE, const float* __restrict__ tO,
    u64* __restrict__ sM2,
    const u64* __restrict__ sex2, const u64* __restrict__ sey2,
    const float* __restrict__ sS0,
    int tid, float c1c, float c2c, float* __restrict__ outrow)
{
    constexpr int HALF = (K-1)/2;
    constexpr int T = PS + 2*HALF;     // <= 32

    // ---- horizontal: moments m1..m5 per (row, column-pair); one point/thread
    if (tid < 8*T) {
        const int row = tid >> 3, pr = tid & 7;
        const int colb = pr*2;
        const float* eB = tE + row*TSTR + colb;
        const float* oB = tO + row*TSTR + colb;
        u64 m1=0ull, m2=0ull, m3=0ull, m4=0ull, m5=0ull;
        #pragma unroll
        for (int dx = 0; dx < K; dx++) {
            const u64 p2 = (dx & 1) ? *(const u64*)(oB + dx - 1)
                                    : *(const u64*)(eB + dx);
            const u64 e2 = sex2[dx];
            u64 t = mul2_(e2, p2);
            m1 = add2_(m1, t);
            t = mul2_(t, p2); m2 = add2_(m2, t);
            t = mul2_(t, p2); m3 = add2_(m3, t);
            t = mul2_(t, p2); m4 = add2_(m4, t);
            t = mul2_(t, p2); m5 = add2_(m5, t);
        }
        u64* d = sM2 + row*MSTR + pr*6;
        ((ulonglong2*)d)[0] = make_ulonglong2(m1, m2);
        ((ulonglong2*)d)[1] = make_ulonglong2(m3, m4);
        ((ulonglong2*)d)[2] = make_ulonglong2(m5, m5);
    }
    __syncthreads();
    if (tid >= 128) return;

    // ---- vertical: S1..S5 per pixel pair (conflict-free LDS.128) ----
    const int r = tid >> 3, pr = tid & 7;
    u64 S1=0ull, S2=0ull, S3=0ull, S4=0ull, S5=0ull;
    #pragma unroll
    for (int dy = 0; dy < K; dy++) {
        const u64 ey2 = sey2[dy];
        const u64* mr = sM2 + (r + dy)*MSTR + pr*6;
        const ulonglong2 L0 = ((const ulonglong2*)mr)[0];
        const ulonglong2 L1 = ((const ulonglong2*)mr)[1];
        const u64 m5 = mr[4];
        S1 = fma2_(ey2, L0.x, S1);
        S2 = fma2_(ey2, L0.y, S2);
        S3 = fma2_(ey2, L1.x, S3);
        S4 = fma2_(ey2, L1.y, S4);
        S5 = fma2_(ey2, m5,   S5);
    }

    // ---- combine: polynomial coefficients from center values (packed) ----
    const int col = pr*2 + HALF;
    const u64 c2v = (HALF & 1) ? *(const u64*)(tO + (r+HALF)*TSTR + col - 1)
                               : *(const u64*)(tE + (r+HALF)*TSTR + col);
    const u64 C1v  = pk2(c1c, c1c);
    const u64 C2v  = pk2(c2c, c2c);
    const u64 ONE2 = pk2(1.f, 1.f);
    const u64 cc2 = mul2_(c2v, c2v);
    const u64 cc4 = mul2_(cc2, cc2);
    const u64 a0 = fma2_(C2v, cc4, fma2_(C1v, cc2, ONE2));
    const u64 t1 = fma2_(pk2(2.f*c2c, 2.f*c2c), cc2, C1v);
    const u64 a1 = mul2_(mul2_(pk2(-2.f,-2.f), c2v), t1);
    const u64 a2 = fma2_(pk2(6.f*c2c, 6.f*c2c), cc2, C1v);
    const u64 a3 = mul2_(pk2(-4.f*c2c, -4.f*c2c), c2v);
    const float s0 = *sS0;
    const u64 S0v = pk2(s0, s0);
    u64 ws = mul2_(a0, S0v);
    ws = fma2_(a1, S1, ws);
    ws = fma2_(a2, S2, ws);
    ws = fma2_(a3, S3, ws);
    ws = fma2_(C2v, S4, ws);
    u64 ac = mul2_(a0, S1);
    ac = fma2_(a1, S2, ac);
    ac = fma2_(a2, S3, ac);
    ac = fma2_(a3, S4, ac);
    ac = fma2_(C2v, S5, ac);
    const float2 wv = upk2(ws), av = upk2(ac);
    float2 res;
    res.x = av.x / (wv.x + 1e-8f);
    res.y = av.y / (wv.y + 1e-8f);
    *(float2*)(outrow + r*HW + pr*2) = res;
}

__global__ __launch_bounds__(256, 6)
void bilateral_kernel(const float* __restrict__ x, float* __restrict__ out) {
    __shared__ __align__(16) float tE[32*TSTR];
    __shared__ __align__(16) float tO[32*TSTR];
    __shared__ __align__(16) u64 sM2[32*MSTR];
    __shared__ u64 sex2[20], sey2[20];
    __shared__ float sS0;
    const int n = blockIdx.x, b = blockIdx.y;
    const int hp = n / GRIDP, wn = n % GRIDP;
    const int tid = threadIdx.x;

    cudaGridDependencySynchronize();            // wait for attn1's g_s/g_max (PDL)

    const float m = __int_as_float(g_max);
    const int half = (int)ceilf(m + 1.0f);
    const int k = 2*half + 1;

    const float* sv = g_s + (b*NPATCH + n)*3;
    const float sx = sv[0], sy = sv[1], sr = sv[2];
    const float ix = -0.5f/(sx*sx), iy = -0.5f/(sy*sy), ir = -0.5f/(sr*sr);
    const float c1c = ir, c2c = 0.5f*ir*ir;

    // stage tile with zero padding (stride TSTR); tO = tile shifted by 1
    const int y0 = hp*PS - half, x0 = wn*PS - half;
    const float* xb = x + b*HW*HW;
    for (int i = tid; i < 1024; i += 256) {
        const int ty = i >> 5, tx = i & 31;
        const int gy = y0 + ty, gx = x0 + tx;
        float v = 0.f;
        if ((unsigned)gy < HW && (unsigned)gx < HW && ty < 2*half+PS && tx < 2*half+PS)
            v = xb[gy*HW + gx];
        tE[ty*TSTR + tx] = v;
        if (tx > 0) tO[ty*TSTR + tx - 1] = v;
    }
    if (tid < k) {
        const float f = (float)(tid - half);
        const float ex = __expf(f*f*ix);
        const float ey = __expf(f*f*iy);
        sex2[tid] = pk2(ex, ex);
        sey2[tid] = pk2(ey, ey);
    }
    __syncthreads();
    if (tid == 0) {
        float se = 0.f, sy2 = 0.f;
        for (int i = 0; i < k; i++) {
            se  += upk2(sex2[i]).x;
            sy2 += upk2(sey2[i]).x;
        }
        sS0 = se * sy2;
    }

    float* outrow = out + (b*HW + hp*PS)*HW + wn*PS;
    switch (k) {
        case 3:  bilat_core2<3 >(tE, tO, sM2, sex2, sey2, &sS0, tid, c1c, c2c, outrow); break;
        case 5:  bilat_core2<5 >(tE, tO, sM2, sex2, sey2, &sS0, tid, c1c, c2c, outrow); break;
        case 7:  bilat_core2<7 >(tE, tO, sM2, sex2, sey2, &sS0, tid, c1c, c2c, outrow); break;
        case 9:  bilat_core2<9 >(tE, tO, sM2, sex2, sey2, &sS0, tid, c1c, c2c, outrow); break;
        case 11: bilat_core2<11>(tE, tO, sM2, sex2, sey2, &sS0, tid, c1c, c2c, outrow); break;
        case 13: bilat_core2<13>(tE, tO, sM2, sex2, sey2, &sS0, tid, c1c, c2c, outrow); break;
        case 15: bilat_core2<15>(tE, tO, sM2, sex2, sey2, &sS0, tid, c1c, c2c, outrow); break;
        case 17: bilat_core2<17>(tE, tO, sM2, sex2, sey2, &sS0, tid, c1c, c2c, outrow); break;
        default: {   // generic fallback (unreachable: sigma cap bounds k <= 17)
            const int r = tid >> 4, cc = tid & 15;
            const float c = tE[(r + half)*TSTR + cc + half];
            float acc = 0.f, wsum = 0.f;
            for (int dy = 0; dy < k; dy++) {
                const float fy = (float)(dy - half);
                const float ey = __expf(fy*fy*iy);
                const float* trow = tE + (r + dy)*TSTR + cc;
                for (int dx = 0; dx < k; dx++) {
                    const float fx = (float)(dx - half);
                    const float p = trow[dx];
                    const float d = c - p;
                    const float w = ey * __expf(fx*fx*ix) * __expf(d*d*ir);
                    wsum += w;
                    acc = fmaf(w, p, acc);
                }
            }
            outrow[r*HW + cc] = acc / (wsum + 1e-8f);
        }
    }
}

// ---------------- PDL launch helper ------------------------------------------
static void launch_pdl(const void* func, dim3 grid, dim3 block, void** args) {
    cudaLaunchConfig_t cfg = {};
    cfg.gridDim = grid;
    cfg.blockDim = block;
    cudaLaunchAttribute attr[1];
    attr[0].id = cudaLaunchAttributeProgrammaticStreamSerialization;
    attr[0].val.programmaticStreamSerializationAllowed = 1;
    cfg.attrs = attr;
    cfg.numAttrs = 1;
    if (cudaLaunchKernelExC(&cfg, func, args) != cudaSuccess) {
        cudaGetLastError();                      // clear; fall back to plain launch
        cudaLaunchKernel(func, grid, block, args, 0, 0);
    }
}

// ---------------- launcher ---------------------------------------------------
extern "C" void kernel_launch(void* const* d_in, const int* in_sizes, int n_in,
                              void* d_out, int out_size) {
    const float* x    = (const float*)d_in[0];
    const float* Wq   = (const float*)d_in[1];
    const float* bq   = (const float*)d_in[2];
    const float* Wk   = (const float*)d_in[3];
    const float* bk   = (const float*)d_in[4];
    const float* Wv   = (const float*)d_in[5];
    const float* bv   = (const float*)d_in[6];
    const float* Wsq  = (const float*)d_in[7];
    const float* bsq  = (const float*)d_in[8];
    const float* Wsk  = (const float*)d_in[9];
    const float* bsk  = (const float*)d_in[10];
    const float* Wsv  = (const float*)d_in[11];
    const float* bsv  = (const float*)d_in[12];
    const float* ln_g = (const float*)d_in[13];
    const float* ln_b = (const float*)d_in[14];
    const float* Wp   = (const float*)d_in[15];
    const float* bp   = (const float*)d_in[16];
    float* out = (float*)d_out;

    // qkv: plain launch (PDL here would race the previous replay's bilateral)
    qkv_kernel<<<dim3(NPATCH/8, NB), 256>>>(x, Wq, bq, Wk, bk, Wv, bv);

    {   // attn0 with PDL over qkv
        void* args[] = {(void*)&Wsq, (void*)&bsq, (void*)&Wsk, (void*)&bsk,
                        (void*)&Wsv, (void*)&bsv};
        launch_pdl((const void*)attn0_kernel, dim3(NPATCH/8, NB), dim3(256), args);
    }
    {   // attn1 with PDL over attn0
        void* args[] = {(void*)&ln_g, (void*)&ln_b, (void*)&Wp, (void*)&bp};
        launch_pdl((const void*)attn1_kernel, dim3(NPATCH/8, NB), dim3(256), args);
    }
    {   // bilateral with PDL over attn1 (sync FIRST, then R8-structure body)
        void* args[] = {(void*)&x, (void*)&out};
        launch_pdl((const void*)bilateral_kernel, dim3(NPATCH, NB), dim3(256), args);
    }
}